// round 2
// baseline (speedup 1.0000x reference)
#include <cuda_runtime.h>

#define NN 200000
#define NT 4
#define EMAX 400000

// ---------------- scratch (no allocation allowed) ----------------
__device__ int   g_cnt[2][NT * NN];     // per-(set, type, dest) edge counts
__device__ int   g_tot[2][NT];          // per-(set, type) edge totals
__device__ int   g_ofs[2][NT];          // per-type start offsets into binned lists
__device__ int   g_fill[2][NT];         // bin cursors
__device__ int   g_src1[EMAX];          // binned sources, shape-1 set
__device__ int   g_src2[2 * EMAX];      // binned sources, shape-2 set
__device__ int   g_dstb[2][EMAX];       // binned dests
__device__ float g_nrmb[2][EMAX];       // binned 1/count norms
__device__ float g_CwT[128 * 128];      // C_w transposed to [d][o]

// ---------------- packed f32x2 helpers ----------------
#define PACK2(r, lo, hi)   asm("mov.b64 %0, {%1, %2};" : "=l"(r) : "f"(lo), "f"(hi))
#define UNPACK2(lo, hi, r) asm("mov.b64 {%0, %1}, %2;" : "=f"(lo), "=f"(hi) : "l"(r))
#define FMA2(acc, a, b)    asm("fma.rn.f32x2 %0, %1, %2, %0;" : "+l"(acc) : "l"(a), "l"(b))

__device__ __forceinline__ void red_v4(float* addr, float a, float b, float c, float d) {
    asm volatile("red.global.add.v4.f32 [%0], {%1, %2, %3, %4};"
                 :: "l"(addr), "f"(a), "f"(b), "f"(c), "f"(d) : "memory");
}

// ---------------- setup kernels ----------------
__global__ void zero_kernel() {
    int i = blockIdx.x * blockDim.x + threadIdx.x;
    if (i < NT * NN) { g_cnt[0][i] = 0; g_cnt[1][i] = 0; }
    if (i < NT) { g_tot[0][i] = 0; g_tot[1][i] = 0; }
}

__global__ void count_kernel(const int* __restrict__ idx, const int* __restrict__ types,
                             int E, int shape, int which) {
    int e = blockIdx.x * blockDim.x + threadIdx.x;
    if (e >= E) return;
    int dest = idx[E * shape + e * shape];
    int t = types[e];
    atomicAdd(&g_cnt[which][t * NN + dest], 1);
    atomicAdd(&g_tot[which][t], 1);
}

__global__ void ofs_kernel() {
    for (int w = 0; w < 2; w++) {
        int s = 0;
        for (int t = 0; t < NT; t++) {
            g_ofs[w][t] = s; g_fill[w][t] = 0; s += g_tot[w][t];
        }
    }
}

template <int SHAPE>
__global__ void bin_kernel(const int* __restrict__ idx, const int* __restrict__ types,
                           int E, int which) {
    int e = blockIdx.x * blockDim.x + threadIdx.x;
    if (e >= E) return;
    int t = types[e];
    int dest = idx[E * SHAPE + e * SHAPE];
    int p = atomicAdd(&g_fill[which][t], 1);
    int q = g_ofs[which][t] + p;
    g_dstb[which][q] = dest;
    g_nrmb[which][q] = 1.0f / (float)g_cnt[which][t * NN + dest];
    if (SHAPE == 1) {
        g_src1[q] = idx[e];
    } else {
        g_src2[q * 2]     = idx[e * 2];
        g_src2[q * 2 + 1] = idx[e * 2 + 1];
    }
}

__global__ void transpose_kernel(const float* __restrict__ Cw) {
    int i = blockIdx.x * blockDim.x + threadIdx.x;
    if (i < 128 * 128) {
        int o = i >> 7, d = i & 127;
        g_CwT[d * 128 + o] = Cw[i];
    }
}

// ---------------- dense: out[n] = x[n] @ CwT + Cb ----------------
// Persistent blocks. CwT staged in smem ONCE per block. 8 warps x 8 nodes per tile.
__global__ void __launch_bounds__(256, 2)
dense_kernel(const float* __restrict__ x, const float* __restrict__ Cb,
             float* __restrict__ out, int n_nodes) {
    extern __shared__ float sm[];
    float* W_s   = sm;                 // 128*128
    float* feats = sm + 128 * 128;     // 8 warps * 8 nodes * 128
    int tid = threadIdx.x, warp = tid >> 5, lane = tid & 31;

    for (int i = tid; i < 128 * 32; i += 256)
        ((float4*)W_s)[i] = ((const float4*)g_CwT)[i];
    __syncthreads();

    float4 bb = ((const float4*)Cb)[lane];
    float* wf = feats + warp * 8 * 128;
    int ntiles = (n_nodes + 63) >> 6;

    for (int tile = blockIdx.x; tile < ntiles; tile += gridDim.x) {
        int node0 = tile * 64 + warp * 8;
        #pragma unroll
        for (int q = 0; q < 8; q++) {
            int n = node0 + q; if (n >= n_nodes) n = n_nodes - 1;
            ((float4*)wf)[q * 32 + lane] = ((const float4*)x)[(size_t)n * 32 + lane];
        }
        __syncwarp();

        unsigned long long acc[8][4];
        #pragma unroll
        for (int q = 0; q < 8; q++)
            #pragma unroll
            for (int c = 0; c < 4; c++) acc[q][c] = 0ull;

        #pragma unroll 2
        for (int k = 0; k < 128; k += 4) {
            float4 a0 = *(const float4*)(W_s + (k + 0) * 128 + lane * 4);
            float4 a1 = *(const float4*)(W_s + (k + 1) * 128 + lane * 4);
            float4 a2 = *(const float4*)(W_s + (k + 2) * 128 + lane * 4);
            float4 a3 = *(const float4*)(W_s + (k + 3) * 128 + lane * 4);
            unsigned long long A01[4], A23[4];
            PACK2(A01[0], a0.x, a1.x); PACK2(A01[1], a0.y, a1.y);
            PACK2(A01[2], a0.z, a1.z); PACK2(A01[3], a0.w, a1.w);
            PACK2(A23[0], a2.x, a3.x); PACK2(A23[1], a2.y, a3.y);
            PACK2(A23[2], a2.z, a3.z); PACK2(A23[3], a2.w, a3.w);
            #pragma unroll
            for (int q = 0; q < 8; q++) {
                ulonglong2 fv = *(const ulonglong2*)(wf + q * 128 + k);
                FMA2(acc[q][0], A01[0], fv.x); FMA2(acc[q][1], A01[1], fv.x);
                FMA2(acc[q][2], A01[2], fv.x); FMA2(acc[q][3], A01[3], fv.x);
                FMA2(acc[q][0], A23[0], fv.y); FMA2(acc[q][1], A23[1], fv.y);
                FMA2(acc[q][2], A23[2], fv.y); FMA2(acc[q][3], A23[3], fv.y);
            }
        }
        #pragma unroll
        for (int q = 0; q < 8; q++) {
            int n = node0 + q;
            if (n < n_nodes) {
                float lo, hi, o0, o1, o2, o3;
                UNPACK2(lo, hi, acc[q][0]); o0 = lo + hi + bb.x;
                UNPACK2(lo, hi, acc[q][1]); o1 = lo + hi + bb.y;
                UNPACK2(lo, hi, acc[q][2]); o2 = lo + hi + bb.z;
                UNPACK2(lo, hi, acc[q][3]); o3 = lo + hi + bb.w;
                ((float4*)out)[(size_t)n * 32 + lane] = make_float4(o0, o1, o2, o3);
            }
        }
        __syncwarp();
    }
}

// ---------------- edge aggregation ----------------
// Block handles ONE type (blockIdx % 4). A[t] staged in smem once. Grid-strides
// over 256-edge tiles of the binned same-type list. 8 warps x 8 edges concurrent.
template <int SHAPE>
__global__ void __launch_bounds__(256, (SHAPE == 1) ? 2 : 1)
edge_kernel(const float* __restrict__ x, const float* __restrict__ A,
            int which, float* __restrict__ out) {
    constexpr int K = SHAPE * 128;
    extern __shared__ float sm[];
    float* A_s   = sm;                        // K*128
    float* feats = A_s + K * 128;             // 8 warps * 8 edges * K
    int*   s_src = (int*)(feats + 64 * K);    // 256*SHAPE
    int*   s_dst = s_src + 256 * SHAPE;       // 256
    float* s_nrm = (float*)(s_dst + 256);     // 256

    int tid = threadIdx.x, warp = tid >> 5, lane = tid & 31;
    int t = blockIdx.x & 3;
    int group = blockIdx.x >> 2, ngroups = gridDim.x >> 2;
    const int* srcs = (SHAPE == 1) ? g_src1 : g_src2;

    // stage A[t]
    const float4* Ag = (const float4*)(A + (size_t)t * K * 128);
    for (int i = tid; i < K * 32; i += 256) ((float4*)A_s)[i] = Ag[i];

    int base_t = g_ofs[which][t];
    int n_t = g_tot[which][t];
    int ntiles = (n_t + 255) >> 8;
    float* wf = feats + warp * 8 * K;
    __syncthreads();

    for (int tile = group; tile < ntiles; tile += ngroups) {
        int p = tile * 256 + tid;
        bool v = (p < n_t);
        int q = base_t + (v ? p : (n_t - 1));
        s_dst[tid] = g_dstb[which][q];
        s_nrm[tid] = v ? g_nrmb[which][q] : 0.0f;
        #pragma unroll
        for (int j = 0; j < SHAPE; j++) s_src[tid * SHAPE + j] = srcs[q * SHAPE + j];
        __syncthreads();

        #pragma unroll
        for (int pass = 0; pass < 4; pass++) {
            int b = warp * 8 + pass * 64;
            // stage features for 8 edges
            #pragma unroll
            for (int e = 0; e < 8; e++) {
                #pragma unroll
                for (int j = 0; j < SHAPE; j++) {
                    int sn = s_src[(b + e) * SHAPE + j];
                    ((float4*)wf)[(e * SHAPE + j) * 32 + lane] =
                        ((const float4*)x)[(size_t)sn * 32 + lane];
                }
            }
            __syncwarp();

            unsigned long long acc[8][4];
            #pragma unroll
            for (int e = 0; e < 8; e++)
                #pragma unroll
                for (int c = 0; c < 4; c++) acc[e][c] = 0ull;

            #pragma unroll 2
            for (int k = 0; k < K; k += 4) {
                float4 a0 = *(const float4*)(A_s + (k + 0) * 128 + lane * 4);
                float4 a1 = *(const float4*)(A_s + (k + 1) * 128 + lane * 4);
                float4 a2 = *(const float4*)(A_s + (k + 2) * 128 + lane * 4);
                float4 a3 = *(const float4*)(A_s + (k + 3) * 128 + lane * 4);
                unsigned long long A01[4], A23[4];
                PACK2(A01[0], a0.x, a1.x); PACK2(A01[1], a0.y, a1.y);
                PACK2(A01[2], a0.z, a1.z); PACK2(A01[3], a0.w, a1.w);
                PACK2(A23[0], a2.x, a3.x); PACK2(A23[1], a2.y, a3.y);
                PACK2(A23[2], a2.z, a3.z); PACK2(A23[3], a2.w, a3.w);
                #pragma unroll
                for (int e = 0; e < 8; e++) {
                    ulonglong2 fv = *(const ulonglong2*)(wf + e * K + k);
                    FMA2(acc[e][0], A01[0], fv.x); FMA2(acc[e][1], A01[1], fv.x);
                    FMA2(acc[e][2], A01[2], fv.x); FMA2(acc[e][3], A01[3], fv.x);
                    FMA2(acc[e][0], A23[0], fv.y); FMA2(acc[e][1], A23[1], fv.y);
                    FMA2(acc[e][2], A23[2], fv.y); FMA2(acc[e][3], A23[3], fv.y);
                }
            }

            #pragma unroll
            for (int e = 0; e < 8; e++) {
                float nv = s_nrm[b + e];
                int d = s_dst[b + e];
                float lo, hi, o0, o1, o2, o3;
                UNPACK2(lo, hi, acc[e][0]); o0 = (lo + hi) * nv;
                UNPACK2(lo, hi, acc[e][1]); o1 = (lo + hi) * nv;
                UNPACK2(lo, hi, acc[e][2]); o2 = (lo + hi) * nv;
                UNPACK2(lo, hi, acc[e][3]); o3 = (lo + hi) * nv;
                red_v4(out + (size_t)d * 128 + lane * 4, o0, o1, o2, o3);
            }
            __syncwarp();
        }
        __syncthreads();
    }
}

// ---------------- launcher ----------------
extern "C" void kernel_launch(void* const* d_in, const int* in_sizes, int n_in,
                              void* d_out, int out_size) {
    const float* x     = (const float*)d_in[0];
    const int*   idx1  = (const int*)d_in[1];
    const int*   type1 = (const int*)d_in[2];
    const int*   idx2  = (const int*)d_in[3];
    const int*   type2 = (const int*)d_in[4];
    const float* Cw    = (const float*)d_in[5];
    const float* Cb    = (const float*)d_in[6];
    const float* A1    = (const float*)d_in[7];
    const float* A2    = (const float*)d_in[8];
    float* out = (float*)d_out;

    int E1v = in_sizes[2];
    int E2v = in_sizes[4];
    int n_nodes = in_sizes[0] / 128;

    int smem_dense = (128 * 128 + 64 * 128) * 4;                       // 96 KB
    int smem_e1 = (128 * 128 + 64 * 128) * 4 + 256 * 3 * 4;            // ~99 KB
    int smem_e2 = (256 * 128 + 64 * 256) * 4 + 256 * 4 * 4;            // ~196 KB

    cudaFuncSetAttribute(dense_kernel, cudaFuncAttributeMaxDynamicSharedMemorySize, smem_dense);
    cudaFuncSetAttribute(edge_kernel<1>, cudaFuncAttributeMaxDynamicSharedMemorySize, smem_e1);
    cudaFuncSetAttribute(edge_kernel<2>, cudaFuncAttributeMaxDynamicSharedMemorySize, smem_e2);

    zero_kernel<<<(NT * NN + 255) / 256, 256>>>();
    count_kernel<<<(E1v + 255) / 256, 256>>>(idx1, type1, E1v, 1, 0);
    count_kernel<<<(E2v + 255) / 256, 256>>>(idx2, type2, E2v, 2, 1);
    ofs_kernel<<<1, 1>>>();
    bin_kernel<1><<<(E1v + 255) / 256, 256>>>(idx1, type1, E1v, 0);
    bin_kernel<2><<<(E2v + 255) / 256, 256>>>(idx2, type2, E2v, 1);
    transpose_kernel<<<(128 * 128 + 255) / 256, 256>>>(Cw);

    dense_kernel<<<296, 256, smem_dense>>>(x, Cb, out, n_nodes);
    edge_kernel<1><<<296, 256, smem_e1>>>(x, A1, 0, out);
    edge_kernel<2><<<148, 256, smem_e2>>>(x, A2, 1, out);
}

// round 5
// speedup vs baseline: 2.3581x; 2.3581x over previous
#include <cuda_runtime.h>
#include <cstdint>

#define NN 200000
#define NT 4
#define EMAX 400000
#define PAD 132

// ---------------- device scratch ----------------
__device__ int   g_cnt[2][NT * NN];
__device__ int   g_tot[2][NT];
__device__ int   g_ofs[2][NT];
__device__ int   g_fill[2][NT];
__device__ int   g_src1[EMAX];
__device__ int   g_src2[2 * EMAX];
__device__ int   g_dstb[2][EMAX];
__device__ float g_nrmb[2][EMAX];
__device__ float g_xr[(size_t)NN * 128];   // tf32-rounded copy of x

// ---------------- helpers ----------------
__device__ __forceinline__ uint32_t tf32_bits(float f) {
    uint32_t r; asm("cvt.rna.tf32.f32 %0, %1;" : "=r"(r) : "f"(f));
    return r;
}
__device__ __forceinline__ float tf32r(float f) {
    return __uint_as_float(tf32_bits(f));
}
__device__ __forceinline__ void red_v4(float* addr, float a, float b, float c, float d) {
    asm volatile("red.global.add.v4.f32 [%0], {%1, %2, %3, %4};"
                 :: "l"(addr), "f"(a), "f"(b), "f"(c), "f"(d) : "memory");
}
__device__ __forceinline__ void mma8(float* c, uint32_t a0, uint32_t a1, uint32_t a2,
                                     uint32_t a3, uint32_t b0, uint32_t b1) {
    asm volatile("mma.sync.aligned.m16n8k8.row.col.f32.tf32.tf32.f32 "
                 "{%0,%1,%2,%3}, {%4,%5,%6,%7}, {%8,%9}, {%0,%1,%2,%3};"
                 : "+f"(c[0]), "+f"(c[1]), "+f"(c[2]), "+f"(c[3])
                 : "r"(a0), "r"(a1), "r"(a2), "r"(a3), "r"(b0), "r"(b1));
}

// ---------------- setup kernels ----------------
__global__ void zero_kernel() {
    int i = blockIdx.x * blockDim.x + threadIdx.x;
    if (i < NT * NN) { g_cnt[0][i] = 0; g_cnt[1][i] = 0; }
    if (i < NT) { g_tot[0][i] = 0; g_tot[1][i] = 0; }
}
__global__ void count_kernel(const int* __restrict__ idx, const int* __restrict__ types,
                             int E, int shape, int which) {
    int e = blockIdx.x * blockDim.x + threadIdx.x;
    if (e >= E) return;
    int dest = idx[E * shape + e * shape];
    int t = types[e];
    atomicAdd(&g_cnt[which][t * NN + dest], 1);
    atomicAdd(&g_tot[which][t], 1);
}
__global__ void ofs_kernel() {
    for (int w = 0; w < 2; w++) {
        int s = 0;
        for (int t = 0; t < NT; t++) { g_ofs[w][t] = s; g_fill[w][t] = 0; s += g_tot[w][t]; }
    }
}
template <int SHAPE>
__global__ void bin_kernel(const int* __restrict__ idx, const int* __restrict__ types,
                           int E, int which) {
    int e = blockIdx.x * blockDim.x + threadIdx.x;
    if (e >= E) return;
    int t = types[e];
    int dest = idx[E * SHAPE + e * SHAPE];
    int p = atomicAdd(&g_fill[which][t], 1);
    int q = g_ofs[which][t] + p;
    g_dstb[which][q] = dest;
    g_nrmb[which][q] = 1.0f / (float)g_cnt[which][t * NN + dest];
    if (SHAPE == 1) g_src1[q] = idx[e];
    else { g_src2[q * 2] = idx[e * 2]; g_src2[q * 2 + 1] = idx[e * 2 + 1]; }
}
__global__ void round_kernel(const float* __restrict__ x) {
    int i = blockIdx.x * blockDim.x + threadIdx.x;
    if (i < NN * 32) {
        float4 v = ((const float4*)x)[i];
        v.x = tf32r(v.x); v.y = tf32r(v.y); v.z = tf32r(v.z); v.w = tf32r(v.w);
        ((float4*)g_xr)[i] = v;
    }
}

// ---------------- dense: out[n] = xr[n] @ Cw^T + Cb (direct store) ----------------
__global__ void __launch_bounds__(256, 1)
dense_mma_kernel(const float* __restrict__ Cw, const float* __restrict__ Cb,
                 float* __restrict__ out, int n_nodes) {
    extern __shared__ float feats[];   // 128 * PAD
    int tid = threadIdx.x, w = tid >> 5, lane = tid & 31;
    int g = lane >> 2, tg = lane & 3;
    int mhalf = w & 1, nq = w >> 1;
    int nb = nq * 32;
    const uint32_t* fb = (const uint32_t*)feats;

    // B fragments in regs: B[k][n] = Cw[n][k]
    uint32_t bfr[16][4][2];
    #pragma unroll
    for (int kc = 0; kc < 16; kc++)
        #pragma unroll
        for (int nc = 0; nc < 4; nc++) {
            int n = nb + nc * 8 + g;
            bfr[kc][nc][0] = tf32_bits(Cw[n * 128 + kc * 8 + tg]);
            bfr[kc][nc][1] = tf32_bits(Cw[n * 128 + kc * 8 + tg + 4]);
        }
    float2 bias[4];
    #pragma unroll
    for (int nc = 0; nc < 4; nc++) {
        int cb = nb + nc * 8 + 2 * tg;
        bias[nc] = make_float2(Cb[cb], Cb[cb + 1]);
    }

    int ntiles = (n_nodes + 127) >> 7;
    for (int tile = blockIdx.x; tile < ntiles; tile += gridDim.x) {
        __syncthreads();
        #pragma unroll
        for (int rr = 0; rr < 16; rr++) {
            int r = w * 16 + rr;
            int n = tile * 128 + r; if (n >= n_nodes) n = n_nodes - 1;
            *(float4*)(feats + r * PAD + lane * 4) =
                ((const float4*)(g_xr + (size_t)n * 128))[lane];
        }
        __syncthreads();

        float acc[4][4][4];
        #pragma unroll
        for (int mc = 0; mc < 4; mc++)
            #pragma unroll
            for (int nc = 0; nc < 4; nc++)
                #pragma unroll
                for (int i = 0; i < 4; i++) acc[mc][nc][i] = 0.f;

        #pragma unroll
        for (int mc = 0; mc < 4; mc++) {
            int R = mhalf * 64 + mc * 16 + g;
            #pragma unroll
            for (int kc = 0; kc < 16; kc++) {
                uint32_t a0 = fb[R * PAD + kc * 8 + tg];
                uint32_t a1 = fb[(R + 8) * PAD + kc * 8 + tg];
                uint32_t a2 = fb[R * PAD + kc * 8 + tg + 4];
                uint32_t a3 = fb[(R + 8) * PAD + kc * 8 + tg + 4];
                #pragma unroll
                for (int nc = 0; nc < 4; nc++)
                    mma8(acc[mc][nc], a0, a1, a2, a3, bfr[kc][nc][0], bfr[kc][nc][1]);
            }
        }
        // direct epilogue: rows R, R+8; cols nb+nc*8+2tg, +1
        #pragma unroll
        for (int mc = 0; mc < 4; mc++) {
            int R = mhalf * 64 + mc * 16 + g;
            int n0 = tile * 128 + R, n1 = n0 + 8;
            #pragma unroll
            for (int nc = 0; nc < 4; nc++) {
                int cb = nb + nc * 8 + 2 * tg;
                if (n0 < n_nodes)
                    *(float2*)(out + (size_t)n0 * 128 + cb) =
                        make_float2(acc[mc][nc][0] + bias[nc].x, acc[mc][nc][1] + bias[nc].y);
                if (n1 < n_nodes)
                    *(float2*)(out + (size_t)n1 * 128 + cb) =
                        make_float2(acc[mc][nc][2] + bias[nc].x, acc[mc][nc][3] + bias[nc].y);
            }
        }
    }
}

// ---------------- edge MMA: 12 units = set1(4 types) + set2(4 types x 2 K-halves) ----
__global__ void __launch_bounds__(256, 1)
edge_mma_kernel(const float* __restrict__ A1, const float* __restrict__ A2,
                float* __restrict__ out) {
    extern __shared__ float feats[];                  // 128 * PAD
    int*   s_dst = (int*)(feats + 128 * PAD);         // 128
    float* s_nrm = (float*)(s_dst + 128);             // 128
    int tid = threadIdx.x, w = tid >> 5, lane = tid & 31;
    int g = lane >> 2, tg = lane & 3;
    int mhalf = w & 1, nq = w >> 1;
    int nb = nq * 32;
    const uint32_t* fb = (const uint32_t*)feats;

    int unit = blockIdx.x % 12, grp = blockIdx.x / 12, ngrp = gridDim.x / 12;
    int set, t, scol;
    const float* W;
    if (unit < 4) { set = 0; t = unit; scol = 0; W = A1 + (size_t)t * 16384; }
    else {
        int u = unit - 4; set = 1; t = u >> 1; scol = u & 1;
        W = A2 + (size_t)t * 32768 + (size_t)scol * 16384;
    }
    const int* srcs = (set == 0) ? g_src1 : g_src2;
    int sstride = (set == 0) ? 1 : 2;

    // B fragments in regs: B[k][n] = W[k*128 + n]
    uint32_t bfr[16][4][2];
    #pragma unroll
    for (int kc = 0; kc < 16; kc++)
        #pragma unroll
        for (int nc = 0; nc < 4; nc++) {
            int n = nb + nc * 8 + g;
            bfr[kc][nc][0] = tf32_bits(W[(kc * 8 + tg) * 128 + n]);
            bfr[kc][nc][1] = tf32_bits(W[(kc * 8 + tg + 4) * 128 + n]);
        }

    int base_t = g_ofs[set][t];
    int n_t = g_tot[set][t];
    int ntiles = (n_t + 127) >> 7;

    for (int tile = grp; tile < ntiles; tile += ngrp) {
        __syncthreads();    // previous scatter done; safe to overwrite feats/meta
        if (tid < 128) {
            int p = tile * 128 + tid;
            bool v = (p < n_t);
            int q = base_t + (v ? p : (n_t - 1));
            s_dst[tid] = g_dstb[set][q];
            s_nrm[tid] = v ? g_nrmb[set][q] : 0.0f;
        }
        // gather feats (src read directly from global; no dependency on meta)
        #pragma unroll
        for (int rr = 0; rr < 16; rr++) {
            int r = w * 16 + rr;
            int p = tile * 128 + r; if (p >= n_t) p = n_t - 1;
            int src = srcs[(base_t + p) * sstride + scol];
            *(float4*)(feats + r * PAD + lane * 4) =
                ((const float4*)(g_xr + (size_t)src * 128))[lane];
        }
        __syncthreads();

        float acc[4][4][4];
        #pragma unroll
        for (int mc = 0; mc < 4; mc++)
            #pragma unroll
            for (int nc = 0; nc < 4; nc++)
                #pragma unroll
                for (int i = 0; i < 4; i++) acc[mc][nc][i] = 0.f;

        #pragma unroll
        for (int mc = 0; mc < 4; mc++) {
            int R = mhalf * 64 + mc * 16 + g;
            #pragma unroll
            for (int kc = 0; kc < 16; kc++) {
                uint32_t a0 = fb[R * PAD + kc * 8 + tg];
                uint32_t a1 = fb[(R + 8) * PAD + kc * 8 + tg];
                uint32_t a2 = fb[R * PAD + kc * 8 + tg + 4];
                uint32_t a3 = fb[(R + 8) * PAD + kc * 8 + tg + 4];
                #pragma unroll
                for (int nc = 0; nc < 4; nc++)
                    mma8(acc[mc][nc], a0, a1, a2, a3, bfr[kc][nc][0], bfr[kc][nc][1]);
            }
        }
        __syncthreads();    // all warps done reading feats
        // write norm-scaled D into feats (transpose for coalesced scatter)
        #pragma unroll
        for (int mc = 0; mc < 4; mc++) {
            int R = mhalf * 64 + mc * 16 + g;
            float n0 = s_nrm[R], n1 = s_nrm[R + 8];
            #pragma unroll
            for (int nc = 0; nc < 4; nc++) {
                int cb = nb + nc * 8 + 2 * tg;
                *(float2*)(feats + R * PAD + cb) =
                    make_float2(acc[mc][nc][0] * n0, acc[mc][nc][1] * n0);
                *(float2*)(feats + (R + 8) * PAD + cb) =
                    make_float2(acc[mc][nc][2] * n1, acc[mc][nc][3] * n1);
            }
        }
        __syncthreads();
        // coalesced scatter (padded rows have nrm 0 -> add 0 to a valid dest)
        #pragma unroll
        for (int rr = 0; rr < 16; rr++) {
            int r = w * 16 + rr;
            int d = s_dst[r];
            float4 v = *(const float4*)(feats + r * PAD + lane * 4);
            red_v4(out + (size_t)d * 128 + lane * 4, v.x, v.y, v.z, v.w);
        }
    }
}

// ---------------- launcher ----------------
extern "C" void kernel_launch(void* const* d_in, const int* in_sizes, int n_in,
                              void* d_out, int out_size) {
    const float* x     = (const float*)d_in[0];
    const int*   idx1  = (const int*)d_in[1];
    const int*   type1 = (const int*)d_in[2];
    const int*   idx2  = (const int*)d_in[3];
    const int*   type2 = (const int*)d_in[4];
    const float* Cw    = (const float*)d_in[5];
    const float* Cb    = (const float*)d_in[6];
    const float* A1    = (const float*)d_in[7];
    const float* A2    = (const float*)d_in[8];
    float* out = (float*)d_out;

    int E1v = in_sizes[2];
    int E2v = in_sizes[4];
    int n_nodes = in_sizes[0] / 128;

    int smem_dense = 128 * PAD * 4;
    int smem_edge  = 128 * PAD * 4 + 128 * 8;

    cudaFuncSetAttribute(dense_mma_kernel, cudaFuncAttributeMaxDynamicSharedMemorySize, smem_dense);
    cudaFuncSetAttribute(edge_mma_kernel, cudaFuncAttributeMaxDynamicSharedMemorySize, smem_edge);

    zero_kernel<<<(NT * NN + 255) / 256, 256>>>();
    count_kernel<<<(E1v + 255) / 256, 256>>>(idx1, type1, E1v, 1, 0);
    count_kernel<<<(E2v + 255) / 256, 256>>>(idx2, type2, E2v, 2, 1);
    ofs_kernel<<<1, 1>>>();
    bin_kernel<1><<<(E1v + 255) / 256, 256>>>(idx1, type1, E1v, 0);
    bin_kernel<2><<<(E2v + 255) / 256, 256>>>(idx2, type2, E2v, 1);
    round_kernel<<<(NN * 32 + 255) / 256, 256>>>(x);

    dense_mma_kernel<<<148, 256, smem_dense>>>(Cw, Cb, out, n_nodes);
    edge_mma_kernel<<<144, 256, smem_edge>>>(A1, A2, out);
}